// round 4
// baseline (speedup 1.0000x reference)
#include <cuda_runtime.h>
#include <math.h>

#define WARPS_PER_BLOCK 8
#define THREADS_PER_BLOCK (WARPS_PER_BLOCK * 32)
#define FULL_MASK 0xffffffffu

// Index width (int32 vs int64) detected from raw words of row_ptr:
//   int32: [0, D, 2D, ...]  -> raw[1] != 0
//   int64: [0,0, D,0, ...]  -> raw[1] == 0 && raw[2] != 0
__device__ __forceinline__ long long load_index(const void* p, long long i, int is64)
{
    return is64 ? ((const long long*)p)[i] : (long long)((const int*)p)[i];
}

// One warp per destination node. Softmax over 16 edge scores, then weighted
// gather-accumulate of 64-float rows (float4 x 16 lanes per row; the two
// half-warps each take 8 of the 16 edges). All 8 gathers are issued
// back-to-back before any FMA consumes them -> 8 loads in flight per warp.
__global__ void __launch_bounds__(THREADS_PER_BLOCK, 4)
gat_aggregate_kernel(const void*   __restrict__ row_ptr_raw,
                     const void*   __restrict__ col_idx_raw,
                     const float*  __restrict__ edge_scores,
                     const float4* __restrict__ node_value4,  // [N, 16] float4
                     float4*       __restrict__ out4,         // [N, 16] float4
                     int num_nodes)
{
    const int node = blockIdx.x * WARPS_PER_BLOCK + (threadIdx.x >> 5);
    if (node >= num_nodes) return;
    const int lane = threadIdx.x & 31;

    // uniform per-grid: detect index width (L2-broadcast loads, ~free)
    const unsigned* rp_raw = (const unsigned*)row_ptr_raw;
    const int is64 = (rp_raw[1] == 0u && rp_raw[2] != 0u) ? 1 : 0;

    const long long start = load_index(row_ptr_raw, node, is64);
    const long long end   = load_index(row_ptr_raw, node + 1, is64);
    const int deg = (int)(end - start);

    const int half = lane >> 4;    // which half-warp
    const int sub  = lane & 15;    // float4 column within the row

    float4 acc = make_float4(0.0f, 0.0f, 0.0f, 0.0f);

    if (deg == 16) {
        // ---- fast path: degree exactly 16 (this dataset) ----
        float s = -INFINITY;
        unsigned c = 0;
        if (lane < 16) {
            s = edge_scores[start + lane];
            c = (unsigned)load_index(col_idx_raw, start + lane, is64);
        }
        float m = s;
        #pragma unroll
        for (int off = 8; off > 0; off >>= 1)
            m = fmaxf(m, __shfl_xor_sync(FULL_MASK, m, off));

        float w = (lane < 16) ? __expf(s - m) : 0.0f;
        float sum = w;
        #pragma unroll
        for (int off = 8; off > 0; off >>= 1)
            sum += __shfl_xor_sync(FULL_MASK, sum, off);

        w *= __frcp_rn(sum);

        // Phase 1: broadcast all 8 (w, col) pairs for this half-warp and
        // issue all 8 gathers back-to-back (maximum MLP).
        float  bw[8];
        float4 v[8];
        #pragma unroll
        for (int e = 0; e < 8; e++) {
            const int edge = 2 * e + half;
            bw[e] = __shfl_sync(FULL_MASK, w, edge);
            const unsigned bc = __shfl_sync(FULL_MASK, c, edge);
            v[e] = node_value4[(size_t)bc * 16 + sub];
        }
        // Phase 2: accumulate.
        #pragma unroll
        for (int e = 0; e < 8; e++) {
            acc.x = fmaf(bw[e], v[e].x, acc.x);
            acc.y = fmaf(bw[e], v[e].y, acc.y);
            acc.z = fmaf(bw[e], v[e].z, acc.z);
            acc.w = fmaf(bw[e], v[e].w, acc.w);
        }

        // combine the two half-warp partial sums
        acc.x += __shfl_xor_sync(FULL_MASK, acc.x, 16);
        acc.y += __shfl_xor_sync(FULL_MASK, acc.y, 16);
        acc.z += __shfl_xor_sync(FULL_MASK, acc.z, 16);
        acc.w += __shfl_xor_sync(FULL_MASK, acc.w, 16);

        if (half == 0)
            out4[(size_t)node * 16 + sub] = acc;
    } else {
        // ---- generic path: any degree (not taken on this dataset) ----
        float m = -INFINITY;
        for (int e = lane; e < deg; e += 32)
            m = fmaxf(m, edge_scores[start + e]);
        #pragma unroll
        for (int off = 16; off > 0; off >>= 1)
            m = fmaxf(m, __shfl_xor_sync(FULL_MASK, m, off));

        float sum = 0.0f;
        for (int e = lane; e < deg; e += 32)
            sum += __expf(edge_scores[start + e] - m);
        #pragma unroll
        for (int off = 16; off > 0; off >>= 1)
            sum += __shfl_xor_sync(FULL_MASK, sum, off);
        const float inv = (deg > 0) ? __frcp_rn(sum) : 0.0f;

        for (int e = half; e < deg; e += 2) {
            const float bs = edge_scores[start + e];
            const unsigned bc = (unsigned)load_index(col_idx_raw, start + e, is64);
            const float bwv = __expf(bs - m) * inv;
            const float4 vv = node_value4[(size_t)bc * 16 + sub];
            acc.x = fmaf(bwv, vv.x, acc.x);
            acc.y = fmaf(bwv, vv.y, acc.y);
            acc.z = fmaf(bwv, vv.z, acc.z);
            acc.w = fmaf(bwv, vv.w, acc.w);
        }
        acc.x += __shfl_xor_sync(FULL_MASK, acc.x, 16);
        acc.y += __shfl_xor_sync(FULL_MASK, acc.y, 16);
        acc.z += __shfl_xor_sync(FULL_MASK, acc.z, 16);
        acc.w += __shfl_xor_sync(FULL_MASK, acc.w, 16);

        if (half == 0)
            out4[(size_t)node * 16 + sub] = acc;
    }
}

extern "C" void kernel_launch(void* const* d_in, const int* in_sizes, int n_in,
                              void* d_out, int out_size)
{
    const void*   row_ptr     = d_in[0];
    const void*   col_idx     = d_in[1];
    const float*  edge_scores = (const float*)d_in[2];
    const float4* node_value4 = (const float4*)d_in[3];
    float4*       out4        = (float4*)d_out;

    const int num_nodes = in_sizes[0] - 1;
    const int grid = (num_nodes + WARPS_PER_BLOCK - 1) / WARPS_PER_BLOCK;

    gat_aggregate_kernel<<<grid, THREADS_PER_BLOCK>>>(
        row_ptr, col_idx, edge_scores, node_value4, out4, num_nodes);
}